// round 11
// baseline (speedup 1.0000x reference)
#include <cuda_runtime.h>
#include <cuda_fp16.h>
#include <cstdint>

// Problem constants
constexpr int Bb = 8;
constexpr int Nn = 1024;
constexpr int Cc = 768;
constexpr int Hh = 12;
constexpr int HDd = 64;
constexpr int Vv = 8;

constexpr int M1  = Bb * Nn;       // 8192
constexpr int MKV = Vv * Bb * Nn;  // 65536
constexpr int KVW = 2 * HDd;       // 128

// ---------------------------------------------------------------------------
// Scratch
// ---------------------------------------------------------------------------
__device__ __half g_qh[M1 * Cc];       // q, fp16
__device__ __half g_kvh[MKV * KVW];    // kv, fp16
__device__ __half g_aoh[M1 * Cc];      // attn output, fp16
__device__ __half g_wq[Cc * Cc];       // fp16 weights
__device__ __half g_wkv[KVW * Cc];
__device__ __half g_wp[Cc * Cc];

__device__ __forceinline__ uint32_t smem_u32(const void* p) {
    uint32_t a;
    asm("{ .reg .u64 t; cvta.to.shared.u64 t, %1; cvt.u32.u64 %0, t; }"
        : "=r"(a) : "l"(p));
    return a;
}

#define CP_ASYNC16(dst, src)                                                  \
    asm volatile("cp.async.ca.shared.global [%0], [%1], 16;\n"                \
                 :: "r"(dst), "l"(src))
#define CP_COMMIT() asm volatile("cp.async.commit_group;\n" ::: "memory")
#define CP_WAIT1()  asm volatile("cp.async.wait_group 1;\n" ::: "memory")

#define MMA_F16(c, a, b)                                                    \
    asm volatile(                                                           \
        "mma.sync.aligned.m16n8k16.row.col.f32.f16.f16.f32 "                \
        "{%0,%1,%2,%3}, {%4,%5,%6,%7}, {%8,%9}, {%0,%1,%2,%3};\n"           \
        : "+f"((c)[0]), "+f"((c)[1]), "+f"((c)[2]), "+f"((c)[3])            \
        : "r"((a)[0]), "r"((a)[1]), "r"((a)[2]), "r"((a)[3]),               \
          "r"((b)[0]), "r"((b)[1]))

#define LDSM_X4(r0, r1, r2, r3, addr)                                       \
    asm volatile(                                                           \
        "ldmatrix.sync.aligned.m8n8.x4.shared.b16 {%0,%1,%2,%3}, [%4];"     \
        : "=r"(r0), "=r"(r1), "=r"(r2), "=r"(r3) : "r"(addr))

// ---------------------------------------------------------------------------
// FP16 warp-MMA GEMM-NT: C = A @ W^T (+bias), fp32 accum.
// CTA tile 256x128, 512 threads, 16 warps in 4M x 4N (warp tile 64x32).
// BK=32, 4-stage cp.async, one barrier per k-tile.
// Cross-warp smem re-read per k16: 4*A(8KB) + 4*B(4KB) = 48KB for 2x the
// FLOPs of the previous 128x128 tile -> half the smem bytes per FLOP.
// Smem rows: 32 halfs padded to 40 (80 B, 16B-aligned, conflict-free LDSM).
// ---------------------------------------------------------------------------
constexpr int STAGES = 4;
constexpr int BK = 32;
constexpr int BM = 256;
constexpr int BN = 128;
constexpr int ROWH = 40;                        // halfs per smem row (80 B)
constexpr int A_TILE_B = BM * ROWH * 2;         // 20480
constexpr int B_TILE_B = BN * ROWH * 2;         // 10240
constexpr int STAGE_BYTES = A_TILE_B + B_TILE_B; // 30720
constexpr int GEMM_SMEM = STAGES * STAGE_BYTES;  // 122880
constexpr int MT_STRIDE = 16 * ROWH * 2;        // 1280 bytes / 16 rows

// OUT_HALF: C is fp16 (qkv outputs). Otherwise fp32 with optional bias.
template <bool STAGE_A, bool OUT_HALF>
__device__ __forceinline__
void gemm_body(const float* __restrict__ Af,    // fp32 A (STAGE_A)
               const __half* __restrict__ Ah,   // fp16 A (!STAGE_A)
               const __half* __restrict__ W,
               const float* __restrict__ bias,
               void* __restrict__ Cv,
               int N, int K, int bm, int bn,
               char* sm, uint32_t sb)
{
    const int t    = threadIdx.x;       // 0..511
    const int wid  = t >> 5;            // 0..15
    const int lane = t & 31;
    const int lq   = lane >> 2;
    const int lr   = lane & 3;

    const int warp_m = (wid & 3) * 64;   // 0,64,128,192
    const int warp_n = (wid >> 2) * 32;  // 0,32,64,96

    // ---- B cp.async: 512 16B chunks (128 rows x 4), 1/thread ----
    const int rB = t >> 2, cB = t & 3;
    const __half* Wp0 = W + (size_t)(bn + rB) * K + cB * 8;
    const uint32_t dB = A_TILE_B + (uint32_t)(rB * ROWH + cB * 8) * 2;

    // ---- fp16-A cp.async: 1024 chunks (256 rows x 4), 2/thread ----
    const int rA0 = t >> 2,          cA0 = t & 3;
    const int rA1 = (t + 512) >> 2,  cA1 = t & 3;
    const __half* Ah0 = Ah + (size_t)(bm + rA0) * K + cA0 * 8;
    const __half* Ah1 = Ah + (size_t)(bm + rA1) * K + cA1 * 8;
    const uint32_t dA0 = (uint32_t)(rA0 * ROWH + cA0 * 8) * 2;
    const uint32_t dA1 = (uint32_t)(rA1 * ROWH + cA1 * 8) * 2;

    // ---- fp32-A staging: 512 tasks (256 rows x 2 16-float chunks), 1/thread
    const int rS  = t >> 1;
    const int chS = t & 1;
    const float* Asrc = Af + (size_t)(bm + rS) * K + chS * 16;
    char* AstsBase = sm + (size_t)rS * (ROWH * 2) + chS * 32;

    auto issue_tile = [&](int kt) {
        const uint32_t base = sb + (uint32_t)(kt % STAGES) * STAGE_BYTES;
        const size_t ko = (size_t)kt * BK;
        CP_ASYNC16(base + dB, Wp0 + ko);
        if (!STAGE_A) {
            CP_ASYNC16(base + dA0, Ah0 + ko);
            CP_ASYNC16(base + dA1, Ah1 + ko);
        }
    };

    float4 av[4];
    auto ldgA = [&](int kt) {
        if (STAGE_A) {
            const float4* p =
                reinterpret_cast<const float4*>(Asrc + (size_t)kt * BK);
            av[0] = p[0]; av[1] = p[1]; av[2] = p[2]; av[3] = p[3];
        }
    };
    auto stsA = [&](int kt) {
        if (STAGE_A) {
            uint32_t h[8];
            #pragma unroll
            for (int j = 0; j < 4; j++) {
                __half2 lo = __floats2half2_rn(av[j].x, av[j].y);
                __half2 hi = __floats2half2_rn(av[j].z, av[j].w);
                h[2 * j]     = *reinterpret_cast<uint32_t*>(&lo);
                h[2 * j + 1] = *reinterpret_cast<uint32_t*>(&hi);
            }
            char* dst = AstsBase + (size_t)(kt % STAGES) * STAGE_BYTES;
            *reinterpret_cast<uint4*>(dst) =
                make_uint4(h[0], h[1], h[2], h[3]);
            *reinterpret_cast<uint4*>(dst + 16) =
                make_uint4(h[4], h[5], h[6], h[7]);
        }
    };

    // ldmatrix per-lane byte offsets within a stage
    const uint32_t aOff =
        (uint32_t)((warp_m + (lane & 15)) * ROWH) * 2 + (lane >> 4) * 16;
    const uint32_t bOff = A_TILE_B
        + (uint32_t)((warp_n + (lane >> 4) * 8 + (lane & 7)) * ROWH) * 2
        + ((lane >> 3) & 1) * 16;

    float acc[4][4][4];
    #pragma unroll
    for (int mt = 0; mt < 4; mt++)
        #pragma unroll
        for (int nt = 0; nt < 4; nt++)
            #pragma unroll
            for (int i = 0; i < 4; i++)
                acc[mt][nt][i] = 0.0f;

    const int NT = K / BK;              // 24

    // ---- prologue ----
    ldgA(0); stsA(0);
    ldgA(1); stsA(1);
    ldgA(2);                            // held for iter 0
    issue_tile(0); CP_COMMIT();
    issue_tile(1); CP_COMMIT();

    for (int kt = 0; kt < NT; kt++) {
        CP_WAIT1();
        __syncthreads();

        if (kt + 2 < NT) {
            stsA(kt + 2);
            if (kt + 3 < NT) ldgA(kt + 3);
            issue_tile(kt + 2);
        }
        CP_COMMIT();

        const uint32_t stBase = sb + (uint32_t)(kt % STAGES) * STAGE_BYTES;

        #pragma unroll
        for (int h = 0; h < 2; h++) {
            const uint32_t kOfs = h * 32;   // 16 halfs
            unsigned afr[4][4];
            unsigned bfr[4][2];
            #pragma unroll
            for (int mt = 0; mt < 4; mt++)
                LDSM_X4(afr[mt][0], afr[mt][1], afr[mt][2], afr[mt][3],
                        stBase + aOff + mt * MT_STRIDE + kOfs);
            #pragma unroll
            for (int p = 0; p < 2; p++)
                LDSM_X4(bfr[2 * p][0], bfr[2 * p][1],
                        bfr[2 * p + 1][0], bfr[2 * p + 1][1],
                        stBase + bOff + p * MT_STRIDE + kOfs);
            #pragma unroll
            for (int mt = 0; mt < 4; mt++)
                #pragma unroll
                for (int nt = 0; nt < 4; nt++)
                    MMA_F16(acc[mt][nt], afr[mt], bfr[nt]);
        }
    }

    // ---- epilogue ----
    #pragma unroll
    for (int mt = 0; mt < 4; mt++) {
        const int row0 = bm + warp_m + mt * 16 + lq;
        #pragma unroll
        for (int nt = 0; nt < 4; nt++) {
            const int col = bn + warp_n + nt * 8 + 2 * lr;
            if (OUT_HALF) {
                __half* C = reinterpret_cast<__half*>(Cv);
                __half2 v01 = __floats2half2_rn(acc[mt][nt][0], acc[mt][nt][1]);
                __half2 v23 = __floats2half2_rn(acc[mt][nt][2], acc[mt][nt][3]);
                *reinterpret_cast<__half2*>(C + (size_t)row0 * N + col) = v01;
                *reinterpret_cast<__half2*>(C + (size_t)(row0 + 8) * N + col) = v23;
            } else {
                float* C = reinterpret_cast<float*>(Cv);
                float b0 = 0.f, b1 = 0.f;
                if (bias) { b0 = bias[col]; b1 = bias[col + 1]; }
                float2 v01 = make_float2(acc[mt][nt][0] + b0, acc[mt][nt][1] + b1);
                float2 v23 = make_float2(acc[mt][nt][2] + b0, acc[mt][nt][3] + b1);
                *reinterpret_cast<float2*>(C + (size_t)row0 * N + col) = v01;
                *reinterpret_cast<float2*>(C + (size_t)(row0 + 8) * N + col) = v23;
            }
        }
    }
}

// Merged q-GEMM + kv-GEMM
constexpr int QK_GRID_Q = (Cc / BN) * (M1 / BM);      // 6*32 = 192
constexpr int QK_GRID   = QK_GRID_Q + (MKV / BM);     // 192+256 = 448

__global__ __launch_bounds__(512, 1)
void qkv_gemm(const float* __restrict__ x,  const __half* __restrict__ wq,
              const float* __restrict__ vp, const __half* __restrict__ wkv,
              __half* __restrict__ q, __half* __restrict__ kv)
{
    extern __shared__ char smc[];
    const uint32_t sb = smem_u32(smc);
    const int bid = blockIdx.x;
    if (bid < QK_GRID_Q) {
        const int bx = bid % (Cc / BN);
        const int by = bid / (Cc / BN);
        gemm_body<true, true>(x, nullptr, wq, nullptr, q, Cc, Cc,
                              by * BM, bx * BN, smc, sb);
    } else {
        const int by = bid - QK_GRID_Q;
        gemm_body<true, true>(vp, nullptr, wkv, nullptr, kv, KVW, Cc,
                              by * BM, 0, smc, sb);
    }
}

__global__ __launch_bounds__(512, 1)
void proj_gemm(const __half* __restrict__ aoh, const __half* __restrict__ wp,
               const float* __restrict__ bias, float* __restrict__ out)
{
    extern __shared__ char smc[];
    const uint32_t sb = smem_u32(smc);
    const int bx = blockIdx.x % (Cc / BN);
    const int by = blockIdx.x / (Cc / BN);
    gemm_body<false, false>(nullptr, aoh, wp, bias, out, Cc, Cc,
                            by * BM, bx * BN, smc, sb);
}

// ---------------------------------------------------------------------------
// Weight pre-conversion to fp16 (one launch)
// ---------------------------------------------------------------------------
constexpr int NW1 = Cc * Cc;
constexpr int NW2 = KVW * Cc;
constexpr int NW_TOT = NW1 + NW2 + NW1;

__global__ void cvt_w_kernel(const float* __restrict__ wq_in,
                             const float* __restrict__ wkv_in,
                             const float* __restrict__ wp_in,
                             __half* __restrict__ wq_o,
                             __half* __restrict__ wkv_o,
                             __half* __restrict__ wp_o)
{
    const int i = blockIdx.x * 256 + threadIdx.x;
    if (i < NW1) {
        wq_o[i] = __float2half_rn(wq_in[i]);
    } else if (i < NW1 + NW2) {
        const int j = i - NW1;
        wkv_o[j] = __float2half_rn(wkv_in[j]);
    } else if (i < NW_TOT) {
        const int j = i - NW1 - NW2;
        wp_o[j] = __float2half_rn(wp_in[j]);
    }
}

// ---------------------------------------------------------------------------
// Fused attention: one CTA per (b,n). fp16 q/kv in, fp32 math, fp16 ao out.
// ---------------------------------------------------------------------------
__global__ __launch_bounds__(256)
void attn_kernel(const __half* __restrict__ q,
                 const __half* __restrict__ kvr,
                 __half* __restrict__ out)
{
    const int bn = blockIdx.x;
    const int t  = threadIdx.x;

    __shared__ __align__(16) __half sq[Cc];         // 1536 B
    __shared__ __align__(16) __half skv[Vv][KVW];   // 2048 B
    __shared__ float slog[Hh * Vv];
    __shared__ float sp[Hh][Vv];

    // Load q row: 96 uint4
    {
        const uint4* src = reinterpret_cast<const uint4*>(q + (size_t)bn * Cc);
        uint4* dst = reinterpret_cast<uint4*>(sq);
        if (t < Cc * 2 / 16) dst[t] = src[t];
    }
    // Load kv rows: 8 x 16 uint4 = 128
    {
        if (t < Vv * KVW * 2 / 16) {
            const int v  = t >> 4;
            const int d4 = t & 15;
            const uint4* src = reinterpret_cast<const uint4*>(
                kvr + ((size_t)v * (Bb * Nn) + bn) * KVW);
            reinterpret_cast<uint4*>(skv[v])[d4] = src[d4];
        }
    }
    __syncthreads();

    // Logits: 96 (h,v) pairs x 8-lane split; 3 tasks per thread.
    #pragma unroll
    for (int rep = 0; rep < 3; rep++) {
        const int task = t + rep * 256;
        const int pair = task >> 3;
        const int sub  = task & 7;
        const int h = pair / Vv;
        const int v = pair % Vv;
        const __half2* q2 =
            reinterpret_cast<const __half2*>(sq + h * HDd + sub * 8);
        const __half2* k2 =
            reinterpret_cast<const __half2*>(skv[v] + sub * 8);
        float a = 0.f;
        #pragma unroll
        for (int j = 0; j < 4; j++) {
            const float2 qa = __half22float2(q2[j]);
            const float2 kb = __half22float2(k2[j]);
            a = fmaf(qa.x, kb.x, a);
            a = fmaf(qa.y, kb.y, a);
        }
        a += __shfl_down_sync(0xffffffffu, a, 4);
        a += __shfl_down_sync(0xffffffffu, a, 2);
        a += __shfl_down_sync(0xffffffffu, a, 1);
        if (sub == 0) slog[pair] = a * 0.125f;
    }
    __syncthreads();

    if (t < Hh) {
        float mx = -1e30f;
        #pragma unroll
        for (int v = 0; v < Vv; v++) mx = fmaxf(mx, slog[t * Vv + v]);
        float e[Vv];
        float s = 0.f;
        #pragma unroll
        for (int v = 0; v < Vv; v++) {
            e[v] = __expf(slog[t * Vv + v] - mx);
            s += e[v];
        }
        const float inv = 1.0f / s;
        #pragma unroll
        for (int v = 0; v < Vv; v++) sp[t][v] = e[v] * inv;
    }
    __syncthreads();

    #pragma unroll
    for (int rep = 0; rep < 3; rep++) {
        const int i = t + rep * 256;
        const int h = i / HDd;
        const int d = i % HDd;
        float a = 0.f;
        #pragma unroll
        for (int v = 0; v < Vv; v++)
            a = fmaf(sp[h][v], __half2float(skv[v][HDd + d]), a);
        out[(size_t)bn * Cc + i] = __float2half_rn(a);
    }
}

// ---------------------------------------------------------------------------
// Launch
// ---------------------------------------------------------------------------
extern "C" void kernel_launch(void* const* d_in, const int* in_sizes, int n_in,
                              void* d_out, int out_size)
{
    const float* x   = (const float*)d_in[0];
    const float* vp  = (const float*)d_in[1];
    const float* Wq  = (const float*)d_in[2];
    const float* Wkv = (const float*)d_in[3];
    const float* Wp  = (const float*)d_in[4];
    const float* bp  = (const float*)d_in[5];
    float* out = (float*)d_out;

    __half *qh, *kvh, *aoh, *wq, *wkv, *wp;
    cudaGetSymbolAddress((void**)&qh,  g_qh);
    cudaGetSymbolAddress((void**)&kvh, g_kvh);
    cudaGetSymbolAddress((void**)&aoh, g_aoh);
    cudaGetSymbolAddress((void**)&wq,  g_wq);
    cudaGetSymbolAddress((void**)&wkv, g_wkv);
    cudaGetSymbolAddress((void**)&wp,  g_wp);

    cudaFuncSetAttribute(qkv_gemm,
                         cudaFuncAttributeMaxDynamicSharedMemorySize,
                         GEMM_SMEM);
    cudaFuncSetAttribute(proj_gemm,
                         cudaFuncAttributeMaxDynamicSharedMemorySize,
                         GEMM_SMEM);

    // 0) pre-convert all weights to fp16
    cvt_w_kernel<<<(NW_TOT + 255) / 256, 256>>>(Wq, Wkv, Wp, wq, wkv, wp);

    // 1+2) q = x @ wq^T  and  kv = vp @ wkv^T  (merged grid, fp16 outputs)
    qkv_gemm<<<QK_GRID, 512, GEMM_SMEM>>>(x, wq, vp, wkv, qh, kvh);

    // 3) fused attention per (b,n): fp16 in/out
    attn_kernel<<<M1, 256>>>(qh, kvh, aoh);

    // 4) out = ao @ wp^T + bproj
    proj_gemm<<<(Cc / BN) * (M1 / BM), 512, GEMM_SMEM>>>(aoh, wp, bp, out);
}

// round 14
// speedup vs baseline: 1.0882x; 1.0882x over previous
#include <cuda_runtime.h>
#include <cuda_fp16.h>
#include <cstdint>

// Problem constants
constexpr int Bb = 8;
constexpr int Nn = 1024;
constexpr int Cc = 768;
constexpr int Hh = 12;
constexpr int HDd = 64;
constexpr int Vv = 8;

constexpr int M1  = Bb * Nn;       // 8192
constexpr int MKV = Vv * Bb * Nn;  // 65536
constexpr int KVW = 2 * HDd;       // 128

// ---------------------------------------------------------------------------
// Scratch
// ---------------------------------------------------------------------------
__device__ __half g_qh[M1 * Cc];       // q, fp16
__device__ __half g_kvh[MKV * KVW];    // kv, fp16
__device__ __half g_aoh[M1 * Cc];      // attn output, fp16
__device__ __half g_wq[Cc * Cc];       // fp16 weights
__device__ __half g_wkv[KVW * Cc];
__device__ __half g_wp[Cc * Cc];

__device__ __forceinline__ uint32_t smem_u32(const void* p) {
    uint32_t a;
    asm("{ .reg .u64 t; cvta.to.shared.u64 t, %1; cvt.u32.u64 %0, t; }"
        : "=r"(a) : "l"(p));
    return a;
}

#define CP_ASYNC16(dst, src)                                                  \
    asm volatile("cp.async.ca.shared.global [%0], [%1], 16;\n"                \
                 :: "r"(dst), "l"(src))
#define CP_COMMIT() asm volatile("cp.async.commit_group;\n" ::: "memory")
#define CP_WAIT1()  asm volatile("cp.async.wait_group 1;\n" ::: "memory")

#define MMA_F16(c, a, b)                                                    \
    asm volatile(                                                           \
        "mma.sync.aligned.m16n8k16.row.col.f32.f16.f16.f32 "                \
        "{%0,%1,%2,%3}, {%4,%5,%6,%7}, {%8,%9}, {%0,%1,%2,%3};\n"           \
        : "+f"((c)[0]), "+f"((c)[1]), "+f"((c)[2]), "+f"((c)[3])            \
        : "r"((a)[0]), "r"((a)[1]), "r"((a)[2]), "r"((a)[3]),               \
          "r"((b)[0]), "r"((b)[1]))

#define LDSM_X4(r0, r1, r2, r3, addr)                                       \
    asm volatile(                                                           \
        "ldmatrix.sync.aligned.m8n8.x4.shared.b16 {%0,%1,%2,%3}, [%4];"     \
        : "=r"(r0), "=r"(r1), "=r"(r2), "=r"(r3) : "r"(addr))

// ---------------------------------------------------------------------------
// FP16 warp-MMA GEMM-NT (R10 config): CTA 128x128, 256 threads, 8 warps
// (4M x 2N, 32x64 warp tiles), BK=32, 4-stage cp.async, one barrier/k-tile.
// Smem rows: 32 halfs padded to 40 (80 B, 16B-aligned, conflict-free LDSM).
// ---------------------------------------------------------------------------
constexpr int STAGES = 4;
constexpr int BK = 32;
constexpr int ROWH = 40;                       // halfs per smem row (80 B)
constexpr int TILE_BYTES_H = 128 * ROWH * 2;   // 10240 per matrix
constexpr int STAGE_BYTES = 2 * TILE_BYTES_H;  // 20480
constexpr int GEMM_SMEM = STAGES * STAGE_BYTES; // 81920
constexpr int MT_STRIDE = 16 * ROWH * 2;       // 1280 bytes / 16 rows

template <bool STAGE_A, bool OUT_HALF>
__device__ __forceinline__
void gemm_body(const float* __restrict__ Af,   // fp32 A (STAGE_A)
               const __half* __restrict__ Ah,  // fp16 A (!STAGE_A)
               const __half* __restrict__ W,
               const float* __restrict__ bias,
               void* __restrict__ Cv,
               int N, int K, int bm, int bn,
               char* sm, uint32_t sb)
{
    const int t    = threadIdx.x;       // 0..255
    const int wid  = t >> 5;
    const int lane = t & 31;
    const int lq   = lane >> 2;
    const int lr   = lane & 3;

    const int warp_m = (wid & 3) * 32;
    const int warp_n = (wid >> 2) * 64;

    // ---- B (and fp16-A) cp.async mapping: 512 16B chunks, 2/thread ----
    const int f0 = t, f1 = t + 256;
    const int rB0 = f0 >> 2, cB0 = f0 & 3;
    const int rB1 = f1 >> 2, cB1 = f1 & 3;
    const __half* W0 = W + (size_t)(bn + rB0) * K + cB0 * 8;
    const __half* W1 = W + (size_t)(bn + rB1) * K + cB1 * 8;
    const uint32_t dB0 = TILE_BYTES_H + (uint32_t)(rB0 * ROWH + cB0 * 8) * 2;
    const uint32_t dB1 = TILE_BYTES_H + (uint32_t)(rB1 * ROWH + cB1 * 8) * 2;

    const __half* Ah0 = Ah + (size_t)(bm + rB0) * K + cB0 * 8;
    const __half* Ah1 = Ah + (size_t)(bm + rB1) * K + cB1 * 8;
    const uint32_t dA0 = (uint32_t)(rB0 * ROWH + cB0 * 8) * 2;
    const uint32_t dA1 = (uint32_t)(rB1 * ROWH + cB1 * 8) * 2;

    // ---- fp32-A staging mapping: row = t>>1, 16-col half = t&1 ----
    const int rA  = t >> 1;
    const int chA = t & 1;
    const float* Asrc = Af + (size_t)(bm + rA) * K + chA * 16;
    char* AstsBase = sm + (size_t)rA * (ROWH * 2) + chA * 32;

    auto issue_tile = [&](int kt) {
        const uint32_t base = sb + (uint32_t)(kt % STAGES) * STAGE_BYTES;
        const size_t ko = (size_t)kt * BK;
        CP_ASYNC16(base + dB0, W0 + ko);
        CP_ASYNC16(base + dB1, W1 + ko);
        if (!STAGE_A) {
            CP_ASYNC16(base + dA0, Ah0 + ko);
            CP_ASYNC16(base + dA1, Ah1 + ko);
        }
    };

    float4 av[4];
    auto ldgA = [&](int kt) {
        if (STAGE_A) {
            const float4* p =
                reinterpret_cast<const float4*>(Asrc + (size_t)kt * BK);
            av[0] = p[0]; av[1] = p[1]; av[2] = p[2]; av[3] = p[3];
        }
    };
    auto stsA = [&](int kt) {
        if (STAGE_A) {
            uint32_t h[8];
            #pragma unroll
            for (int j = 0; j < 4; j++) {
                __half2 lo = __floats2half2_rn(av[j].x, av[j].y);
                __half2 hi = __floats2half2_rn(av[j].z, av[j].w);
                h[2 * j]     = *reinterpret_cast<uint32_t*>(&lo);
                h[2 * j + 1] = *reinterpret_cast<uint32_t*>(&hi);
            }
            char* dst = AstsBase + (size_t)(kt % STAGES) * STAGE_BYTES;
            *reinterpret_cast<uint4*>(dst) =
                make_uint4(h[0], h[1], h[2], h[3]);
            *reinterpret_cast<uint4*>(dst + 16) =
                make_uint4(h[4], h[5], h[6], h[7]);
        }
    };

    // ldmatrix per-lane byte offsets within a stage
    const uint32_t aOff =
        (uint32_t)((warp_m + ((lane >> 3) & 1) * 8 + (lane & 7)) * ROWH) * 2
        + (lane >> 4) * 16;
    const uint32_t bOff = TILE_BYTES_H
        + (uint32_t)((warp_n + (lane >> 4) * 8 + (lane & 7)) * ROWH) * 2
        + ((lane >> 3) & 1) * 16;

    float acc[2][8][4];
    #pragma unroll
    for (int mt = 0; mt < 2; mt++)
        #pragma unroll
        for (int nt = 0; nt < 8; nt++)
            #pragma unroll
            for (int i = 0; i < 4; i++)
                acc[mt][nt][i] = 0.0f;

    const int NT = K / BK;              // 24

    // ---- prologue ----
    ldgA(0); stsA(0);
    ldgA(1); stsA(1);
    ldgA(2);                            // held for iter 0
    issue_tile(0); CP_COMMIT();
    issue_tile(1); CP_COMMIT();

    for (int kt = 0; kt < NT; kt++) {
        CP_WAIT1();
        __syncthreads();

        if (kt + 2 < NT) {
            stsA(kt + 2);
            if (kt + 3 < NT) ldgA(kt + 3);
            issue_tile(kt + 2);
        }
        CP_COMMIT();

        const uint32_t stBase = sb + (uint32_t)(kt % STAGES) * STAGE_BYTES;

        unsigned afr[2][2][4];
        unsigned bfr[2][8][2];
        #pragma unroll
        for (int h = 0; h < 2; h++) {
            const uint32_t kOfs = h * 32;   // 16 halfs = 32 B
            #pragma unroll
            for (int mt = 0; mt < 2; mt++)
                LDSM_X4(afr[h][mt][0], afr[h][mt][1],
                        afr[h][mt][2], afr[h][mt][3],
                        stBase + aOff + mt * MT_STRIDE + kOfs);
            #pragma unroll
            for (int p = 0; p < 4; p++)
                LDSM_X4(bfr[h][2 * p][0], bfr[h][2 * p][1],
                        bfr[h][2 * p + 1][0], bfr[h][2 * p + 1][1],
                        stBase + bOff + p * MT_STRIDE + kOfs);
        }
        #pragma unroll
        for (int h = 0; h < 2; h++)
            #pragma unroll
            for (int mt = 0; mt < 2; mt++)
                #pragma unroll
                for (int nt = 0; nt < 8; nt++)
                    MMA_F16(acc[mt][nt], afr[h][mt], bfr[h][nt]);
    }

    // ---- epilogue ----
    #pragma unroll
    for (int mt = 0; mt < 2; mt++) {
        const int row0 = bm + warp_m + mt * 16 + lq;
        #pragma unroll
        for (int nt = 0; nt < 8; nt++) {
            const int col = bn + warp_n + nt * 8 + 2 * lr;
            if (OUT_HALF) {
                __half* C = reinterpret_cast<__half*>(Cv);
                __half2 v01 = __floats2half2_rn(acc[mt][nt][0], acc[mt][nt][1]);
                __half2 v23 = __floats2half2_rn(acc[mt][nt][2], acc[mt][nt][3]);
                *reinterpret_cast<__half2*>(C + (size_t)row0 * N + col) = v01;
                *reinterpret_cast<__half2*>(C + (size_t)(row0 + 8) * N + col) = v23;
            } else {
                float* C = reinterpret_cast<float*>(Cv);
                float b0 = 0.f, b1 = 0.f;
                if (bias) { b0 = bias[col]; b1 = bias[col + 1]; }
                float2 v01 = make_float2(acc[mt][nt][0] + b0, acc[mt][nt][1] + b1);
                float2 v23 = make_float2(acc[mt][nt][2] + b0, acc[mt][nt][3] + b1);
                *reinterpret_cast<float2*>(C + (size_t)row0 * N + col) = v01;
                *reinterpret_cast<float2*>(C + (size_t)(row0 + 8) * N + col) = v23;
            }
        }
    }
}

// Merged q-GEMM + kv-GEMM
constexpr int QK_GRID_Q = (Cc / 128) * (M1 / 128);    // 384
constexpr int QK_GRID   = QK_GRID_Q + (MKV / 128);    // 896

__global__ __launch_bounds__(256, 2)
void qkv_gemm(const float* __restrict__ x,  const __half* __restrict__ wq,
              const float* __restrict__ vp, const __half* __restrict__ wkv,
              __half* __restrict__ q, __half* __restrict__ kv)
{
    extern __shared__ char smc[];
    const uint32_t sb = smem_u32(smc);
    const int bid = blockIdx.x;
    if (bid < QK_GRID_Q) {
        const int bx = bid % (Cc / 128);
        const int by = bid / (Cc / 128);
        gemm_body<true, true>(x, nullptr, wq, nullptr, q, Cc, Cc,
                              by * 128, bx * 128, smc, sb);
    } else {
        const int by = bid - QK_GRID_Q;
        gemm_body<true, true>(vp, nullptr, wkv, nullptr, kv, KVW, Cc,
                              by * 128, 0, smc, sb);
    }
}

__global__ __launch_bounds__(256, 2)
void proj_gemm(const __half* __restrict__ aoh, const __half* __restrict__ wp,
               const float* __restrict__ bias, float* __restrict__ out)
{
    extern __shared__ char smc[];
    const uint32_t sb = smem_u32(smc);
    const int bx = blockIdx.x % (Cc / 128);
    const int by = blockIdx.x / (Cc / 128);
    gemm_body<false, false>(nullptr, aoh, wp, bias, out, Cc, Cc,
                            by * 128, bx * 128, smc, sb);
}

// ---------------------------------------------------------------------------
// Weight pre-conversion to fp16 (one launch)
// ---------------------------------------------------------------------------
constexpr int NW1 = Cc * Cc;
constexpr int NW2 = KVW * Cc;
constexpr int NW_TOT = NW1 + NW2 + NW1;

__global__ void cvt_w_kernel(const float* __restrict__ wq_in,
                             const float* __restrict__ wkv_in,
                             const float* __restrict__ wp_in,
                             __half* __restrict__ wq_o,
                             __half* __restrict__ wkv_o,
                             __half* __restrict__ wp_o)
{
    const int i = blockIdx.x * 256 + threadIdx.x;
    if (i < NW1) {
        wq_o[i] = __float2half_rn(wq_in[i]);
    } else if (i < NW1 + NW2) {
        const int j = i - NW1;
        wkv_o[j] = __float2half_rn(wkv_in[j]);
    } else if (i < NW_TOT) {
        const int j = i - NW1 - NW2;
        wp_o[j] = __float2half_rn(wp_in[j]);
    }
}

// ---------------------------------------------------------------------------
// Fused attention (R11's proven kernel): one CTA per (b,n).
// fp16 q/kv in, fp32 math, fp16 ao out.
// ---------------------------------------------------------------------------
__global__ __launch_bounds__(256)
void attn_kernel(const __half* __restrict__ q,
                 const __half* __restrict__ kvr,
                 __half* __restrict__ out)
{
    const int bn = blockIdx.x;
    const int t  = threadIdx.x;

    __shared__ __align__(16) __half sq[Cc];         // 1536 B
    __shared__ __align__(16) __half skv[Vv][KVW];   // 2048 B
    __shared__ float slog[Hh * Vv];
    __shared__ float sp[Hh][Vv];

    // Load q row: 96 uint4
    {
        const uint4* src = reinterpret_cast<const uint4*>(q + (size_t)bn * Cc);
        uint4* dst = reinterpret_cast<uint4*>(sq);
        if (t < Cc * 2 / 16) dst[t] = src[t];
    }
    // Load kv rows: 8 x 16 uint4 = 128
    {
        if (t < Vv * KVW * 2 / 16) {
            const int v  = t >> 4;
            const int d4 = t & 15;
            const uint4* src = reinterpret_cast<const uint4*>(
                kvr + ((size_t)v * (Bb * Nn) + bn) * KVW);
            reinterpret_cast<uint4*>(skv[v])[d4] = src[d4];
        }
    }
    __syncthreads();

    // Logits: 96 (h,v) pairs x 8-lane split; 3 tasks per thread.
    #pragma unroll
    for (int rep = 0; rep < 3; rep++) {
        const int task = t + rep * 256;
        const int pair = task >> 3;
        const int sub  = task & 7;
        const int h = pair / Vv;
        const int v = pair % Vv;
        const __half2* q2 =
            reinterpret_cast<const __half2*>(sq + h * HDd + sub * 8);
        const __half2* k2 =
            reinterpret_cast<const __half2*>(skv[v] + sub * 8);
        float a = 0.f;
        #pragma unroll
        for (int j = 0; j < 4; j++) {
            const float2 qa = __half22float2(q2[j]);
            const float2 kb = __half22float2(k2[j]);
            a = fmaf(qa.x, kb.x, a);
            a = fmaf(qa.y, kb.y, a);
        }
        a += __shfl_down_sync(0xffffffffu, a, 4);
        a += __shfl_down_sync(0xffffffffu, a, 2);
        a += __shfl_down_sync(0xffffffffu, a, 1);
        if (sub == 0) slog[pair] = a * 0.125f;
    }
    __syncthreads();

    if (t < Hh) {
        float mx = -1e30f;
        #pragma unroll
        for (int v = 0; v < Vv; v++) mx = fmaxf(mx, slog[t * Vv + v]);
        float e[Vv];
        float s = 0.f;
        #pragma unroll
        for (int v = 0; v < Vv; v++) {
            e[v] = __expf(slog[t * Vv + v] - mx);
            s += e[v];
        }
        const float inv = 1.0f / s;
        #pragma unroll
        for (int v = 0; v < Vv; v++) sp[t][v] = e[v] * inv;
    }
    __syncthreads();

    #pragma unroll
    for (int rep = 0; rep < 3; rep++) {
        const int i = t + rep * 256;
        const int h = i / HDd;
        const int d = i % HDd;
        float a = 0.f;
        #pragma unroll
        for (int v = 0; v < Vv; v++)
            a = fmaf(sp[h][v], __half2float(skv[v][HDd + d]), a);
        out[(size_t)bn * Cc + i] = __float2half_rn(a);
    }
}

// ---------------------------------------------------------------------------
// Launch
// ---------------------------------------------------------------------------
extern "C" void kernel_launch(void* const* d_in, const int* in_sizes, int n_in,
                              void* d_out, int out_size)
{
    const float* x   = (const float*)d_in[0];
    const float* vp  = (const float*)d_in[1];
    const float* Wq  = (const float*)d_in[2];
    const float* Wkv = (const float*)d_in[3];
    const float* Wp  = (const float*)d_in[4];
    const float* bp  = (const float*)d_in[5];
    float* out = (float*)d_out;

    __half *qh, *kvh, *aoh, *wq, *wkv, *wp;
    cudaGetSymbolAddress((void**)&qh,  g_qh);
    cudaGetSymbolAddress((void**)&kvh, g_kvh);
    cudaGetSymbolAddress((void**)&aoh, g_aoh);
    cudaGetSymbolAddress((void**)&wq,  g_wq);
    cudaGetSymbolAddress((void**)&wkv, g_wkv);
    cudaGetSymbolAddress((void**)&wp,  g_wp);

    cudaFuncSetAttribute(qkv_gemm,
                         cudaFuncAttributeMaxDynamicSharedMemorySize,
                         GEMM_SMEM);
    cudaFuncSetAttribute(proj_gemm,
                         cudaFuncAttributeMaxDynamicSharedMemorySize,
                         GEMM_SMEM);

    // 0) pre-convert all weights to fp16
    cvt_w_kernel<<<(NW_TOT + 255) / 256, 256>>>(Wq, Wkv, Wp, wq, wkv, wp);

    // 1+2) q = x @ wq^T  and  kv = vp @ wkv^T  (merged grid, fp16 outputs)
    qkv_gemm<<<QK_GRID, 256, GEMM_SMEM>>>(x, wq, vp, wkv, qh, kvh);

    // 3) fused attention per (b,n): fp16 in/out
    attn_kernel<<<M1, 256>>>(qh, kvh, aoh);

    // 4) out = ao @ wp^T + bproj
    proj_gemm<<<(Cc / 128) * (M1 / 128), 256, GEMM_SMEM>>>(aoh, wp, bp, out);
}